// round 3
// baseline (speedup 1.0000x reference)
#include <cuda_runtime.h>
#include <cuda_bf16.h>

#define T_STEPS 2048
#define BATCH   2048
#define HID     8
#define LAYERS  4

__device__ __forceinline__ float ex2_approx(float x) {
    float r; asm("ex2.approx.f32 %0, %1;" : "=f"(r) : "f"(x)); return r;
}
__device__ __forceinline__ float rcp_approx(float x) {
    float r; asm("rcp.approx.f32 %0, %1;" : "=f"(r) : "f"(x)); return r;
}
// tanh(z) = 1 - 2/(exp(2z)+1), exp(2z) = 2^(z * 2*log2(e))
__device__ __forceinline__ float tanh_fast(float z) {
    float e = ex2_approx(z * 2.8853900817779268f);
    return fmaf(-2.0f, rcp_approx(e + 1.0f), 1.0f);
}

__global__ __launch_bounds__(32, 1)
void rnn_wavefront_kernel(const float* __restrict__ x,
                          const float* __restrict__ initial_h,
                          const float* __restrict__ w_ih0,
                          const float* __restrict__ w_ih,
                          const float* __restrict__ w_hh,
                          const float* __restrict__ b_ih,
                          const float* __restrict__ b_hh,
                          const float* __restrict__ w_lin,
                          const float* __restrict__ b_lin,
                          float* __restrict__ out)
{
    __shared__ float xs[T_STEPS];

    const int lane  = threadIdx.x;       // 0..31
    const int g     = lane >> 3;         // layer group 0..3
    const int j     = lane & 7;          // hidden unit 0..7
    const int gbase = g << 3;            // first lane of own group
    const int pbase = (g == 0) ? 0 : (gbase - 8);  // prev-layer group (g0: dummy, weights=0)
    const int bsel  = BATCH - 1;         // only batch element that reaches the output

    // Prefetch the single relevant batch column of x into SMEM (off the chain).
    for (int t = lane; t < T_STEPS; t += 32)
        xs[t] = x[(size_t)t * BATCH + bsel];

    // Per-lane weights in registers.
    float whh[8], win[8];
#pragma unroll
    for (int k = 0; k < 8; k++) {
        whh[k] = w_hh[(g * HID + j) * HID + k];
        win[k] = (g == 0) ? 0.0f : w_ih[((g - 1) * HID + j) * HID + k];
    }
    const float wx = (g == 0) ? w_ih0[j] : 0.0f;
    const float bc = b_ih[g * HID + j] + b_hh[g * HID + j];
    const float wl = (g == 3) ? w_lin[j] : 0.0f;
    const float bl = b_lin[0];

    float h = initial_h[((size_t)g * BATCH + bsel) * HID + j];

    __syncwarp();

    const unsigned FULL = 0xffffffffu;
    float xt = xs[0];

    for (int i = 0; i < T_STEPS + LAYERS - 1; i++) {
        // Gather pre-update state (warp-synchronous: all lanes still hold iter i-1 values).
        float hk0 = __shfl_sync(FULL, h, gbase + 0);
        float hk1 = __shfl_sync(FULL, h, gbase + 1);
        float hk2 = __shfl_sync(FULL, h, gbase + 2);
        float hk3 = __shfl_sync(FULL, h, gbase + 3);
        float hk4 = __shfl_sync(FULL, h, gbase + 4);
        float hk5 = __shfl_sync(FULL, h, gbase + 5);
        float hk6 = __shfl_sync(FULL, h, gbase + 6);
        float hk7 = __shfl_sync(FULL, h, gbase + 7);
        float pk0 = __shfl_sync(FULL, h, pbase + 0);
        float pk1 = __shfl_sync(FULL, h, pbase + 1);
        float pk2 = __shfl_sync(FULL, h, pbase + 2);
        float pk3 = __shfl_sync(FULL, h, pbase + 3);
        float pk4 = __shfl_sync(FULL, h, pbase + 4);
        float pk5 = __shfl_sync(FULL, h, pbase + 5);
        float pk6 = __shfl_sync(FULL, h, pbase + 6);
        float pk7 = __shfl_sync(FULL, h, pbase + 7);

        // 16 FMAs across 4 accumulators (tree to cut chain depth).
        float a0 = bc, a1 = wx * xt, a2 = 0.0f, a3 = 0.0f;
        a0 = fmaf(whh[0], hk0, a0);
        a1 = fmaf(whh[1], hk1, a1);
        a2 = fmaf(whh[2], hk2, a2);
        a3 = fmaf(whh[3], hk3, a3);
        a0 = fmaf(whh[4], hk4, a0);
        a1 = fmaf(whh[5], hk5, a1);
        a2 = fmaf(whh[6], hk6, a2);
        a3 = fmaf(whh[7], hk7, a3);
        a0 = fmaf(win[0], pk0, a0);
        a1 = fmaf(win[1], pk1, a1);
        a2 = fmaf(win[2], pk2, a2);
        a3 = fmaf(win[3], pk3, a3);
        a0 = fmaf(win[4], pk4, a0);
        a1 = fmaf(win[5], pk5, a1);
        a2 = fmaf(win[6], pk6, a2);
        a3 = fmaf(win[7], pk7, a3);

        float z  = (a0 + a1) + (a2 + a3);
        float hn = tanh_fast(z);

        // Group g's first valid update is iteration i == g (time 0, from initial_h).
        // Updates at i >= T+g are garbage but provably never consumed.
        if (i >= g) h = hn;

        // Output projection for layer 3 (t = i-3). Issues inside tanh's shadow.
        float p = h * wl;
        p += __shfl_xor_sync(FULL, p, 1, 8);
        p += __shfl_xor_sync(FULL, p, 2, 8);
        p += __shfl_xor_sync(FULL, p, 4, 8);
        if (lane == 24 && i >= 3)
            out[i - 3] = p + bl;

        // Prefetch next x (off the chain; LDS hidden behind tanh).
        int nx = i + 1;
        xt = (nx < T_STEPS) ? xs[nx] : 0.0f;
    }
}

extern "C" void kernel_launch(void* const* d_in, const int* in_sizes, int n_in,
                              void* d_out, int out_size) {
    const float* x         = (const float*)d_in[0];
    const float* initial_h = (const float*)d_in[1];
    const float* w_ih0     = (const float*)d_in[2];
    const float* w_ih      = (const float*)d_in[3];
    const float* w_hh      = (const float*)d_in[4];
    const float* b_ih      = (const float*)d_in[5];
    const float* b_hh      = (const float*)d_in[6];
    const float* w_lin     = (const float*)d_in[7];
    const float* b_lin     = (const float*)d_in[8];
    float* out = (float*)d_out;

    rnn_wavefront_kernel<<<1, 32>>>(x, initial_h, w_ih0, w_ih, w_hh,
                                    b_ih, b_hh, w_lin, b_lin, out);
}

// round 5
// speedup vs baseline: 1.5902x; 1.5902x over previous
#include <cuda_runtime.h>
#include <cuda_bf16.h>

#define T_STEPS 2048
#define BATCH   2048
#define HID     8
#define LAYERS  4

// Scratch: layer-3 hidden state per timestep (written by RNN warp, reduced by kernel 2).
__device__ float g_h3[T_STEPS * HID];

__device__ __forceinline__ float ex2_approx(float x) {
    float r; asm("ex2.approx.f32 %0, %1;" : "=f"(r) : "f"(x)); return r;
}
__device__ __forceinline__ float rcp_approx(float x) {
    float r; asm("rcp.approx.f32 %0, %1;" : "=f"(r) : "f"(x)); return r;
}

__global__ __launch_bounds__(32, 1)
void rnn_wavefront_kernel(const float* __restrict__ x,
                          const float* __restrict__ initial_h,
                          const float* __restrict__ w_ih0,
                          const float* __restrict__ w_ih,
                          const float* __restrict__ w_hh,
                          const float* __restrict__ b_ih,
                          const float* __restrict__ b_hh)
{
    __shared__ float xs[T_STEPS + 8];   // padded: tail reads in the last 3 iters are
                                        // in-bounds zeros, never consumed.

    const int lane  = threadIdx.x;       // 0..31
    const int g     = lane >> 3;         // layer 0..3
    const int j     = lane & 7;          // hidden unit 0..7
    const int gbase = g << 3;
    const int pbase = (g == 0) ? 0 : (gbase - 8);
    const int bsel  = BATCH - 1;         // only batch element that reaches the output
    const bool is_l3 = (g == 3);

    for (int t = lane; t < T_STEPS; t += 32)
        xs[t] = x[(size_t)t * BATCH + bsel];
    if (lane < 8) xs[T_STEPS + lane] = 0.0f;

    // Pre-scale everything by c = 2*log2(e) so tanh needs no leading multiply:
    // tanh(s) with z = c*s  ->  1 - 2/(2^z + 1)
    const float C = 2.8853900817779268f;

    float whh[8], win[8];
#pragma unroll
    for (int k = 0; k < 8; k++) {
        whh[k] = C * w_hh[(g * HID + j) * HID + k];
        win[k] = (g == 0) ? 0.0f : C * w_ih[((g - 1) * HID + j) * HID + k];
    }
    const float wx = (g == 0) ? C * w_ih0[j] : 0.0f;
    const float bc = C * (b_ih[g * HID + j] + b_hh[g * HID + j]);

    float h = initial_h[((size_t)g * BATCH + bsel) * HID + j];

    __syncwarp();
    const unsigned FULL = 0xffffffffu;
    float xt = xs[0];

    // One wavefront step. Chain: SHFL(26) -> FMA tree -> adds -> ex2/rcp tanh (40).
    // FMA operand order matches shuffle issue order so early arrivals feed early FMAs.
#define RNN_STEP(HN_OUT)                                                     \
    {                                                                        \
        float hk0 = __shfl_sync(FULL, h, gbase + 0);                         \
        float hk1 = __shfl_sync(FULL, h, gbase + 1);                         \
        float hk2 = __shfl_sync(FULL, h, gbase + 2);                         \
        float hk3 = __shfl_sync(FULL, h, gbase + 3);                         \
        float hk4 = __shfl_sync(FULL, h, gbase + 4);                         \
        float hk5 = __shfl_sync(FULL, h, gbase + 5);                         \
        float hk6 = __shfl_sync(FULL, h, gbase + 6);                         \
        float hk7 = __shfl_sync(FULL, h, gbase + 7);                         \
        float pk0 = __shfl_sync(FULL, h, pbase + 0);                         \
        float pk1 = __shfl_sync(FULL, h, pbase + 1);                         \
        float pk2 = __shfl_sync(FULL, h, pbase + 2);                         \
        float pk3 = __shfl_sync(FULL, h, pbase + 3);                         \
        float pk4 = __shfl_sync(FULL, h, pbase + 4);                         \
        float pk5 = __shfl_sync(FULL, h, pbase + 5);                         \
        float pk6 = __shfl_sync(FULL, h, pbase + 6);                         \
        float pk7 = __shfl_sync(FULL, h, pbase + 7);                         \
        float a0 = bc, a1 = wx * xt, a2 = 0.0f, a3 = 0.0f;                   \
        a0 = fmaf(whh[0], hk0, a0);                                          \
        a1 = fmaf(whh[1], hk1, a1);                                          \
        a2 = fmaf(whh[2], hk2, a2);                                          \
        a3 = fmaf(whh[3], hk3, a3);                                          \
        a0 = fmaf(whh[4], hk4, a0);                                          \
        a1 = fmaf(whh[5], hk5, a1);                                          \
        a2 = fmaf(whh[6], hk6, a2);                                          \
        a3 = fmaf(whh[7], hk7, a3);                                          \
        a0 = fmaf(win[0], pk0, a0);                                          \
        a1 = fmaf(win[1], pk1, a1);                                          \
        a2 = fmaf(win[2], pk2, a2);                                          \
        a3 = fmaf(win[3], pk3, a3);                                          \
        a0 = fmaf(win[4], pk4, a0);                                          \
        a1 = fmaf(win[5], pk5, a1);                                          \
        a2 = fmaf(win[6], pk6, a2);                                          \
        a3 = fmaf(win[7], pk7, a3);                                          \
        float z = (a0 + a1) + (a2 + a3);                                     \
        float e = ex2_approx(z);                                             \
        HN_OUT  = fmaf(-2.0f, rcp_approx(e + 1.0f), 1.0f);                   \
    }

    // Prologue i = 0..2: staggered warm-up (layer g first updates at i == g).
#pragma unroll
    for (int i = 0; i < 3; i++) {
        float hn;
        RNN_STEP(hn);
        if (i >= g) h = hn;
        xt = xs[i + 1];
    }

    // Main loop i = 3..2050: unconditional update; layer-3 h at iter i is t = i-3.
    // Store is a fire-and-forget STG — never on the dependency chain.
    for (int i = 3; i < T_STEPS + LAYERS - 1; i++) {
        float hn;
        RNN_STEP(hn);
        h = hn;
        if (is_l3) g_h3[(i - 3) * HID + j] = h;
        xt = xs[i + 1];
    }
#undef RNN_STEP
}

// Grid-parallel epilogue: out[t] = b_lin + sum_j h3[t][j] * w_lin[j]
__global__ __launch_bounds__(256)
void rnn_proj_kernel(const float* __restrict__ w_lin,
                     const float* __restrict__ b_lin,
                     float* __restrict__ out)
{
    int t = blockIdx.x * blockDim.x + threadIdx.x;
    if (t >= T_STEPS) return;
    const float4* s = reinterpret_cast<const float4*>(&g_h3[t * HID]);
    float4 a = s[0], b = s[1];
    float r = b_lin[0];
    r = fmaf(a.x, w_lin[0], r);
    r = fmaf(a.y, w_lin[1], r);
    r = fmaf(a.z, w_lin[2], r);
    r = fmaf(a.w, w_lin[3], r);
    r = fmaf(b.x, w_lin[4], r);
    r = fmaf(b.y, w_lin[5], r);
    r = fmaf(b.z, w_lin[6], r);
    r = fmaf(b.w, w_lin[7], r);
    out[t] = r;
}

extern "C" void kernel_launch(void* const* d_in, const int* in_sizes, int n_in,
                              void* d_out, int out_size) {
    const float* x         = (const float*)d_in[0];
    const float* initial_h = (const float*)d_in[1];
    const float* w_ih0     = (const float*)d_in[2];
    const float* w_ih      = (const float*)d_in[3];
    const float* w_hh      = (const float*)d_in[4];
    const float* b_ih      = (const float*)d_in[5];
    const float* b_hh      = (const float*)d_in[6];
    const float* w_lin     = (const float*)d_in[7];
    const float* b_lin     = (const float*)d_in[8];
    float* out = (float*)d_out;

    rnn_wavefront_kernel<<<1, 32>>>(x, initial_h, w_ih0, w_ih, w_hh, b_ih, b_hh);
    rnn_proj_kernel<<<(T_STEPS + 255) / 256, 256>>>(w_lin, b_lin, out);
}

// round 8
// speedup vs baseline: 1.9873x; 1.2497x over previous
#include <cuda_runtime.h>
#include <cuda_bf16.h>
#include <cstdint>

#define T_STEPS 2048
#define BATCH   2048
#define HID     8
#define LAYERS  4

// Scratch: layer-3 state in r-space (h = 1 - 2r), written by RNN warp, reduced by kernel 2.
__device__ float g_r3[T_STEPS * HID];

__device__ __forceinline__ float ex2_approx(float x) {
    float r; asm("ex2.approx.f32 %0, %1;" : "=f"(r) : "f"(x)); return r;
}
__device__ __forceinline__ float rcp_approx(float x) {
    float r; asm("rcp.approx.f32 %0, %1;" : "=f"(r) : "f"(x)); return r;
}
__device__ __forceinline__ uint64_t pack2(float lo, float hi) {
    uint64_t d; asm("mov.b64 %0, {%1, %2};" : "=l"(d) : "f"(lo), "f"(hi)); return d;
}
__device__ __forceinline__ void unpack2(uint64_t v, float& a, float& b) {
    asm("mov.b64 {%0, %1}, %2;" : "=f"(a), "=f"(b) : "l"(v));
}
__device__ __forceinline__ uint64_t fma2(uint64_t a, uint64_t b, uint64_t c) {
    uint64_t d; asm("fma.rn.f32x2 %0, %1, %2, %3;" : "=l"(d) : "l"(a), "l"(b), "l"(c)); return d;
}
__device__ __forceinline__ uint64_t mul2(uint64_t a, uint64_t b) {
    uint64_t d; asm("mul.rn.f32x2 %0, %1, %2;" : "=l"(d) : "l"(a), "l"(b)); return d;
}
__device__ __forceinline__ uint64_t add2(uint64_t a, uint64_t b) {
    uint64_t d; asm("add.rn.f32x2 %0, %1, %2;" : "=l"(d) : "l"(a), "l"(b)); return d;
}

__global__ __launch_bounds__(32, 1)
void rnn_wavefront_kernel(const float* __restrict__ x,
                          const float* __restrict__ initial_h,
                          const float* __restrict__ w_ih0,
                          const float* __restrict__ w_ih,
                          const float* __restrict__ w_hh,
                          const float* __restrict__ b_ih,
                          const float* __restrict__ b_hh)
{
    // Ping-pong state buffers (r-space). 16B aligned for LDS.128 gathers.
    __shared__ __align__(16) float hb0[32];
    __shared__ __align__(16) float hb1[32];
    __shared__ float xs[T_STEPS + 8];   // zero-padded tail: last iters read defined zeros

    const int lane  = threadIdx.x;       // 0..31
    const int g     = lane >> 3;         // layer 0..3
    const int j     = lane & 7;          // hidden unit 0..7
    const int gbase = g << 3;
    const int pbase = g ? (gbase - 8) : 0;  // prev layer slice (g0: dummy, weights=0)
    const int bsel  = BATCH - 1;         // only batch element that reaches the output
    const bool is_l3 = (g == 3);

    for (int t = lane; t < T_STEPS; t += 32)
        xs[t] = x[(size_t)t * BATCH + bsel];
    if (lane < 8) xs[T_STEPS + lane] = 0.0f;

    // r-space algebra: h = tanh(s) = 1 - 2r, r = 1/(e^{2s}+1) = rcp(2^(C*s)+1), C = 2*log2(e).
    // Consumer fold: sum_k w_k h_k = sum_k w_k + sum_k (-2 w_k) r_k  ->  w' = -2C*w,
    // bias' = C*(b_ih + b_hh + sum w_hh + sum w_ih).
    const float C = 2.8853900817779268f;

    float wh[8], wi[8];
    float swh = 0.0f, swi = 0.0f;
#pragma unroll
    for (int k = 0; k < 8; k++) {
        float a = w_hh[(g * HID + j) * HID + k];
        float b = g ? w_ih[((g - 1) * HID + j) * HID + k] : 0.0f;
        swh += a; swi += b;
        wh[k] = -2.0f * C * a;
        wi[k] = -2.0f * C * b;
    }
    const float bias2 = C * (b_ih[g * HID + j] + b_hh[g * HID + j] + swh + swi);
    const float wx2   = g ? 0.0f : C * w_ih0[j];

    uint64_t whp[4], wip[4];
#pragma unroll
    for (int k = 0; k < 4; k++) {
        whp[k] = pack2(wh[2 * k], wh[2 * k + 1]);
        wip[k] = pack2(wi[2 * k], wi[2 * k + 1]);
    }
    const uint64_t bias_pack = pack2(bias2, 0.0f);

    // Initial state in r-space: r = (1 - h)/2  (consistent with h = 1 - 2r).
    float r = 0.5f * (1.0f - initial_h[((size_t)g * BATCH + bsel) * HID + j]);
    hb0[lane] = r;
    __syncwarp();

    float xt = xs[0];

    // Core step: 4x LDS.128 gather (prev-iter r's) -> 8 packed f32x2 FMA/MUL ->
    // packed reduce -> ex2/rcp. RN_OUT gets the new r.
#define STEP_CORE(RD, RN_OUT)                                                \
    {                                                                        \
        ulonglong2 gv  = *reinterpret_cast<const ulonglong2*>(&RD[gbase]);   \
        ulonglong2 gv2 = *reinterpret_cast<const ulonglong2*>(&RD[gbase+4]); \
        ulonglong2 pv  = *reinterpret_cast<const ulonglong2*>(&RD[pbase]);   \
        ulonglong2 pv2 = *reinterpret_cast<const ulonglong2*>(&RD[pbase+4]); \
        uint64_t acc0 = fma2(whp[0], gv.x,  bias_pack);                      \
        uint64_t acc1 = fma2(whp[1], gv.y,  pack2(wx2 * xt, 0.0f));          \
        uint64_t acc2 = mul2(whp[2], gv2.x);                                 \
        uint64_t acc3 = mul2(whp[3], gv2.y);                                 \
        acc0 = fma2(wip[0], pv.x,  acc0);                                    \
        acc1 = fma2(wip[1], pv.y,  acc1);                                    \
        acc2 = fma2(wip[2], pv2.x, acc2);                                    \
        acc3 = fma2(wip[3], pv2.y, acc3);                                    \
        uint64_t s = add2(add2(acc0, acc2), add2(acc1, acc3));               \
        float zl, zh; unpack2(s, zl, zh);                                    \
        float z = zl + zh;                                                   \
        RN_OUT = rcp_approx(ex2_approx(z) + 1.0f);                           \
    }

    // Prologue step (staggered warm-up: layer g first updates at i == g).
#define PSTEP(RD, WR, I)                                                     \
    {                                                                        \
        float rn;                                                            \
        STEP_CORE(RD, rn);                                                   \
        r = ((I) >= g) ? rn : r;                                             \
        WR[lane] = r;                                                        \
        xt = xs[(I) + 1];                                                    \
    }

    // Main step: unconditional update + fire-and-forget l3 store (off the chain).
#define MSTEP(RD, WR, I)                                                     \
    {                                                                        \
        float rn;                                                            \
        STEP_CORE(RD, rn);                                                   \
        r = rn;                                                              \
        WR[lane] = r;                                                        \
        if (is_l3) g_r3[((I) - 3) * HID + j] = r;                            \
        xt = xs[(I) + 1];                                                    \
    }

    PSTEP(hb0, hb1, 0)
    PSTEP(hb1, hb0, 1)
    PSTEP(hb0, hb1, 2)

    // i = 3..2050 (2048 iters), unrolled x2 so buffer parity is compile-time.
    for (int i = 3; i < T_STEPS + LAYERS - 1; i += 2) {
        MSTEP(hb1, hb0, i)
        MSTEP(hb0, hb1, i + 1)
    }

#undef STEP_CORE
#undef PSTEP
#undef MSTEP
}

// Grid-parallel epilogue in r-space:
// out[t] = b_lin + sum_j wl_j (1 - 2 r_j) = (b_lin + sum wl) + sum (-2 wl_j) r_j
__global__ __launch_bounds__(256)
void rnn_proj_kernel(const float* __restrict__ w_lin,
                     const float* __restrict__ b_lin,
                     float* __restrict__ out)
{
    int t = blockIdx.x * blockDim.x + threadIdx.x;
    if (t >= T_STEPS) return;
    float wl0 = w_lin[0], wl1 = w_lin[1], wl2 = w_lin[2], wl3 = w_lin[3];
    float wl4 = w_lin[4], wl5 = w_lin[5], wl6 = w_lin[6], wl7 = w_lin[7];
    float s = b_lin[0] + wl0 + wl1 + wl2 + wl3 + wl4 + wl5 + wl6 + wl7;
    const float4* p = reinterpret_cast<const float4*>(&g_r3[t * HID]);
    float4 a = p[0], b = p[1];
    s = fmaf(-2.0f * wl0, a.x, s);
    s = fmaf(-2.0f * wl1, a.y, s);
    s = fmaf(-2.0f * wl2, a.z, s);
    s = fmaf(-2.0f * wl3, a.w, s);
    s = fmaf(-2.0f * wl4, b.x, s);
    s = fmaf(-2.0f * wl5, b.y, s);
    s = fmaf(-2.0f * wl6, b.z, s);
    s = fmaf(-2.0f * wl7, b.w, s);
    out[t] = s;
}

extern "C" void kernel_launch(void* const* d_in, const int* in_sizes, int n_in,
                              void* d_out, int out_size) {
    const float* x         = (const float*)d_in[0];
    const float* initial_h = (const float*)d_in[1];
    const float* w_ih0     = (const float*)d_in[2];
    const float* w_ih      = (const float*)d_in[3];
    const float* w_hh      = (const float*)d_in[4];
    const float* b_ih      = (const float*)d_in[5];
    const float* b_hh      = (const float*)d_in[6];
    const float* w_lin     = (const float*)d_in[7];
    const float* b_lin     = (const float*)d_in[8];
    float* out = (float*)d_out;

    rnn_wavefront_kernel<<<1, 32>>>(x, initial_h, w_ih0, w_ih, w_hh, b_ih, b_hh);
    rnn_proj_kernel<<<(T_STEPS + 255) / 256, 256>>>(w_lin, b_lin, out);
}

// round 9
// speedup vs baseline: 2.2341x; 1.1242x over previous
#include <cuda_runtime.h>
#include <cuda_bf16.h>
#include <cstdint>

#define T_STEPS 2048
#define BATCH   2048
#define HID     8
#define LAYERS  4

// Scratch: layer-3 state in r-space (h = 1 - 2r), written by RNN warp, reduced by kernel 2.
__device__ float g_r3[T_STEPS * HID];

__device__ __forceinline__ float ex2_approx(float x) {
    float r; asm("ex2.approx.f32 %0, %1;" : "=f"(r) : "f"(x)); return r;
}
__device__ __forceinline__ float rcp_approx(float x) {
    float r; asm("rcp.approx.f32 %0, %1;" : "=f"(r) : "f"(x)); return r;
}
__device__ __forceinline__ uint64_t pack2(float lo, float hi) {
    uint64_t d; asm("mov.b64 %0, {%1, %2};" : "=l"(d) : "f"(lo), "f"(hi)); return d;
}
__device__ __forceinline__ void unpack2(uint64_t v, float& a, float& b) {
    asm("mov.b64 {%0, %1}, %2;" : "=f"(a), "=f"(b) : "l"(v));
}
__device__ __forceinline__ uint64_t fma2(uint64_t a, uint64_t b, uint64_t c) {
    uint64_t d; asm("fma.rn.f32x2 %0, %1, %2, %3;" : "=l"(d) : "l"(a), "l"(b), "l"(c)); return d;
}
__device__ __forceinline__ uint64_t mul2(uint64_t a, uint64_t b) {
    uint64_t d; asm("mul.rn.f32x2 %0, %1, %2;" : "=l"(d) : "l"(a), "l"(b)); return d;
}
__device__ __forceinline__ uint64_t add2(uint64_t a, uint64_t b) {
    uint64_t d; asm("add.rn.f32x2 %0, %1, %2;" : "=l"(d) : "l"(a), "l"(b)); return d;
}

__global__ __launch_bounds__(32, 1)
void rnn_wavefront_kernel(const float* __restrict__ x,
                          const float* __restrict__ initial_h,
                          const float* __restrict__ w_ih0,
                          const float* __restrict__ w_ih,
                          const float* __restrict__ w_hh,
                          const float* __restrict__ b_ih,
                          const float* __restrict__ b_hh)
{
    // Ping-pong state buffers (r-space). At iteration I, ALL reads hit the fresh
    // buffer F = buf[(I+1)%2] (written end of I-1); writes go to W = buf[I%2].
    __shared__ __align__(16) float hb0[32];
    __shared__ __align__(16) float hb1[32];
    __shared__ float xs[T_STEPS + 8];   // zero-padded tail (reads up to xs[2054])

    const int lane  = threadIdx.x;       // 0..31
    const int g     = lane >> 3;         // layer 0..3
    const int j     = lane & 7;          // hidden unit 0..7
    const int gbase = g << 3;
    const int pbase = g ? (gbase - 8) : 0;  // prev layer slice (g0: dummy, wip=0)
    const int bsel  = BATCH - 1;
    const bool is_l3 = (g == 3);
    const int  start = g << 1;           // wavefront stagger 2: first update at I=2g

    for (int t = lane; t < T_STEPS; t += 32)
        xs[t] = x[(size_t)t * BATCH + bsel];
    if (lane < 8) xs[T_STEPS + lane] = 0.0f;

    // r-space: h = 1 - 2r, r = rcp(2^(C*s)+1), C = 2*log2(e).
    // w' = -2C*w ; bias' = C*(b_ih + b_hh + sum w_hh + sum w_ih).
    const float C = 2.8853900817779268f;

    float wh[8], wi[8];
    float swh = 0.0f, swi = 0.0f;
#pragma unroll
    for (int k = 0; k < 8; k++) {
        float a = w_hh[(g * HID + j) * HID + k];
        float b = g ? w_ih[((g - 1) * HID + j) * HID + k] : 0.0f;
        swh += a; swi += b;
        wh[k] = -2.0f * C * a;
        wi[k] = -2.0f * C * b;
    }
    const float bias2 = C * (b_ih[g * HID + j] + b_hh[g * HID + j] + swh + swi);
    const float wx2   = g ? 0.0f : C * w_ih0[j];

    uint64_t whp[4], wip[4];
#pragma unroll
    for (int k = 0; k < 4; k++) {
        whp[k] = pack2(wh[2 * k], wh[2 * k + 1]);
        wip[k] = pack2(wi[2 * k], wi[2 * k + 1]);
    }

    float r = 0.5f * (1.0f - initial_h[((size_t)g * BATCH + bsel) * HID + j]);
    hb0[lane] = r;
    hb1[lane] = r;
    __syncwarp();

    // BASE for iteration 0 (valid only for g=0; others recomputed before first use).
    uint64_t basep = pack2(bias2 + wx2 * xs[0], 0.0f);

    // ── Critical half: own-group recurrence only.
    //   LDS gv (2x128b) -> 2-deep fma2 -> add2 -> hadd -> ex2 -> +1 -> rcp
    // ── Shadow half: build next iteration's BASE from prev-group state (same fresh
    //   buffer: r_{g-1} as of I-1 is exactly what layer g consumes at I+1 under
    //   stagger 2), plus bias and x-term. Runs under the MUFU latency.
#define STEP_CORE(F, I, RN_OUT)                                              \
    {                                                                        \
        ulonglong2 gv  = *reinterpret_cast<const ulonglong2*>(&F[gbase]);    \
        ulonglong2 gv2 = *reinterpret_cast<const ulonglong2*>(&F[gbase+4]);  \
        ulonglong2 pv  = *reinterpret_cast<const ulonglong2*>(&F[pbase]);    \
        ulonglong2 pv2 = *reinterpret_cast<const ulonglong2*>(&F[pbase+4]);  \
        uint64_t acc0 = fma2(whp[0], gv.x, basep);                           \
        uint64_t acc1 = mul2(whp[1], gv.y);                                  \
        acc0 = fma2(whp[2], gv2.x, acc0);                                    \
        acc1 = fma2(whp[3], gv2.y, acc1);                                    \
        uint64_t s = add2(acc0, acc1);                                       \
        float zl, zh; unpack2(s, zl, zh);                                    \
        float z = zl + zh;                                                   \
        float e = ex2_approx(z);                                             \
        RN_OUT  = rcp_approx(e + 1.0f);                                      \
        /* shadow: BASE for iteration I+1 */                                 \
        float xq = wx2 * xs[(I) + 1];                                        \
        uint64_t pc0 = fma2(wip[0], pv.x, pack2(bias2 + xq, 0.0f));          \
        uint64_t pc1 = mul2(wip[1], pv.y);                                   \
        pc0 = fma2(wip[2], pv2.x, pc0);                                      \
        pc1 = fma2(wip[3], pv2.y, pc1);                                      \
        uint64_t ps = add2(pc0, pc1);                                        \
        float pl, ph; unpack2(ps, pl, ph);                                   \
        basep = pack2(pl + ph, 0.0f);                                        \
    }

    // Prologue (I = 0..5): predicated update, buffer stays consistent.
#define PSTEP(F, W, I)                                                       \
    {                                                                        \
        float rn;                                                            \
        STEP_CORE(F, I, rn);                                                 \
        r = ((I) >= start) ? rn : r;                                         \
        W[lane] = r;                                                         \
    }

    // Main (I = 6..2053): unconditional; layer-3 value at I is t = I-6.
#define MSTEP(F, W, I)                                                       \
    {                                                                        \
        float rn;                                                            \
        STEP_CORE(F, I, rn);                                                 \
        r = rn;                                                              \
        W[lane] = r;                                                         \
        if (is_l3) g_r3[((I) - 6) * HID + j] = r;                            \
    }

    PSTEP(hb1, hb0, 0)
    PSTEP(hb0, hb1, 1)
    PSTEP(hb1, hb0, 2)
    PSTEP(hb0, hb1, 3)
    PSTEP(hb1, hb0, 4)
    PSTEP(hb0, hb1, 5)

    // 2048 iterations, unrolled x4 (compile-time buffer parity).
    for (int i = 6; i < T_STEPS + 6; i += 4) {
        MSTEP(hb1, hb0, i)
        MSTEP(hb0, hb1, i + 1)
        MSTEP(hb1, hb0, i + 2)
        MSTEP(hb0, hb1, i + 3)
    }

#undef STEP_CORE
#undef PSTEP
#undef MSTEP
}

// Grid-parallel epilogue in r-space:
// out[t] = (b_lin + sum wl) + sum (-2 wl_j) r_j
__global__ __launch_bounds__(256)
void rnn_proj_kernel(const float* __restrict__ w_lin,
                     const float* __restrict__ b_lin,
                     float* __restrict__ out)
{
    int t = blockIdx.x * blockDim.x + threadIdx.x;
    if (t >= T_STEPS) return;
    float wl0 = w_lin[0], wl1 = w_lin[1], wl2 = w_lin[2], wl3 = w_lin[3];
    float wl4 = w_lin[4], wl5 = w_lin[5], wl6 = w_lin[6], wl7 = w_lin[7];
    float s = b_lin[0] + wl0 + wl1 + wl2 + wl3 + wl4 + wl5 + wl6 + wl7;
    const float4* p = reinterpret_cast<const float4*>(&g_r3[t * HID]);
    float4 a = p[0], b = p[1];
    s = fmaf(-2.0f * wl0, a.x, s);
    s = fmaf(-2.0f * wl1, a.y, s);
    s = fmaf(-2.0f * wl2, a.z, s);
    s = fmaf(-2.0f * wl3, a.w, s);
    s = fmaf(-2.0f * wl4, b.x, s);
    s = fmaf(-2.0f * wl5, b.y, s);
    s = fmaf(-2.0f * wl6, b.z, s);
    s = fmaf(-2.0f * wl7, b.w, s);
    out[t] = s;
}

extern "C" void kernel_launch(void* const* d_in, const int* in_sizes, int n_in,
                              void* d_out, int out_size) {
    const float* x         = (const float*)d_in[0];
    const float* initial_h = (const float*)d_in[1];
    const float* w_ih0     = (const float*)d_in[2];
    const float* w_ih      = (const float*)d_in[3];
    const float* w_hh      = (const float*)d_in[4];
    const float* b_ih      = (const float*)d_in[5];
    const float* b_hh      = (const float*)d_in[6];
    const float* w_lin     = (const float*)d_in[7];
    const float* b_lin     = (const float*)d_in[8];
    float* out = (float*)d_out;

    rnn_wavefront_kernel<<<1, 32>>>(x, initial_h, w_ih0, w_ih, w_hh, b_ih, b_hh);
    rnn_proj_kernel<<<(T_STEPS + 255) / 256, 256>>>(w_lin, b_lin, out);
}